// round 6
// baseline (speedup 1.0000x reference)
#include <cuda_runtime.h>
#include <cuda_bf16.h>

#define EMB 32
#define NUM_RADIAL 16
#define MAX_Z 128
#define EPB 128   // edges per block == threads per block

typedef unsigned long long ull;

__constant__ float c_Wr[NUM_RADIAL * EMB];   // 2 KB
__constant__ float c_W3[EMB * EMB];          // 4 KB  (rows 64..95 of W_dense)
__constant__ float c_br[EMB];

__device__ __align__(16) float g_emb1[MAX_Z * EMB];
__device__ __align__(16) float g_emb2[MAX_Z * EMB];

__global__ void precompute_emb_kernel(const float* __restrict__ emb_table,
                                      const float* __restrict__ W_dense,
                                      const float* __restrict__ b_dense,
                                      int num_z)
{
    int z = blockIdx.x;
    int j = threadIdx.x;
    if (z >= MAX_Z || j >= EMB) return;
    if (z >= num_z) { g_emb1[z*EMB+j] = 0.0f; g_emb2[z*EMB+j] = 0.0f; return; }

    float acc1 = b_dense[j];
    float acc2 = 0.0f;
#pragma unroll
    for (int k = 0; k < EMB; ++k) {
        float e = emb_table[z * EMB + k];
        acc1 += e * W_dense[k * EMB + j];
        acc2 += e * W_dense[(EMB + k) * EMB + j];
    }
    g_emb1[z * EMB + j] = acc1;
    g_emb2[z * EMB + j] = acc2;
}

__device__ __forceinline__ ull pk2(float lo, float hi) {
    ull r; asm("mov.b64 %0, {%1, %2};" : "=l"(r) : "f"(lo), "f"(hi)); return r;
}
__device__ __forceinline__ void upk2(ull v, float& lo, float& hi) {
    asm("mov.b64 {%0, %1}, %2;" : "=f"(lo), "=f"(hi) : "l"(v));
}
__device__ __forceinline__ ull ffma2(ull a, ull b, ull c) {
    ull d; asm("fma.rn.f32x2 %0, %1, %2, %3;" : "=l"(d) : "l"(a), "l"(b), "l"(c)); return d;
}

__device__ __forceinline__ float silu_f(float s) {
    float z = __expf(-s);
    return __fdividef(s, 1.0f + z);
}

__global__ __launch_bounds__(EPB)
void dimenet_edge_kernel(const float* __restrict__ d_ij,
                         const float* __restrict__ frequencies,
                         const int*   __restrict__ Z,
                         const int*   __restrict__ idnb_i,
                         const int*   __restrict__ idnb_j,
                         float* __restrict__ out,
                         int E, int N)
{
    // Gather buffer: SG[c][r], c = 16B-chunk (0..7), r = row (0..255):
    //   rows 0..127  = emb1 row for local edge r
    //   rows 128..255= emb2 row for local edge r-128
    // Reused later as output staging SO[c][edge] (c*128 + e), 16KB of the 32KB.
    __shared__ __align__(16) float4 SG[8 * 256];   // 32 KB
    __shared__ int sZi[EPB];
    __shared__ int sZj[EPB];

    const int tid = threadIdx.x;
    const int e   = blockIdx.x * EPB + tid;
    const bool valid = (e < E);
    const int es = valid ? e : (E - 1);

    // ---- per-edge scalar inputs ----
    const float d = d_ij[es];
    int ni = idnb_i[es], nj = idnb_j[es];
    ni = min(max(ni, 0), N - 1);  nj = min(max(nj, 0), N - 1);
    int zi = Z[ni], zj = Z[nj];
    sZi[tid] = min(max(zi, 0), MAX_Z - 1);
    sZj[tid] = min(max(zj, 0), MAX_Z - 1);
    const float f0 = frequencies[0];
    __syncthreads();

    // ---- Phase A: cooperative gather of 256 rows, 4 rows per warp-instr ----
#pragma unroll
    for (int i = 0; i < 16; ++i) {
        int chunk = i * EPB + tid;       // 0..2047
        int r = chunk >> 3;              // 0..255
        int c = chunk & 7;               // 0..7
        int el  = r & 127;
        int z   = (r < 128) ? sZi[el] : sZj[el];
        const float* base = (r < 128) ? g_emb1 : g_emb2;
        const float4* src = reinterpret_cast<const float4*>(base) + z * 8 + c;
        SG[c * 256 + r] = __ldg(src);
    }

    // ---- rbf basis (independent of gather; overlaps LDG latency) ----
    const float x = d * 0.2f;
    const float x2 = x * x;
    const float x4 = x2 * x2;
    const float x5 = x4 * x;
    float env = 1.0f / x + x5 * (-28.0f + x * (48.0f - 21.0f * x));
    env = (x < 1.0f) ? env : 0.0f;

    float s, c0;
    sincosf(f0 * x, &s, &c0);
    const float twoc = 2.0f * c0;

    float rbf[NUM_RADIAL];
    {
        float sm1 = 0.0f, sk = s;
#pragma unroll
        for (int k = 0; k < NUM_RADIAL; ++k) {
            rbf[k] = env * sk;
            float sp1 = twoc * sk - sm1;
            sm1 = sk; sk = sp1;
        }
    }

    // ---- t = silu(rbf @ W_rbf + b_rbf)  (constant-memory weights) ----
    ull tp[EMB / 2];
    {
        const ull* br2 = reinterpret_cast<const ull*>(c_br);
#pragma unroll
        for (int j2 = 0; j2 < EMB / 2; ++j2) tp[j2] = br2[j2];
#pragma unroll
        for (int k = 0; k < NUM_RADIAL; ++k) {
            const ull rb = pk2(rbf[k], rbf[k]);
            const ull* w2 = reinterpret_cast<const ull*>(c_Wr + k * EMB);
#pragma unroll
            for (int j2 = 0; j2 < EMB / 2; ++j2)
                tp[j2] = ffma2(rb, w2[j2], tp[j2]);
        }
    }
    float t[EMB];
#pragma unroll
    for (int j2 = 0; j2 < EMB / 2; ++j2) {
        float a, b;
        upk2(tp[j2], a, b);
        t[2*j2] = silu_f(a); t[2*j2+1] = silu_f(b);
    }

    __syncthreads();   // gather complete

    // ---- Phase B: acc = emb1[zi] + emb2[zj] from smem (conflict-free LDS) ----
    ull acc[EMB / 2];
#pragma unroll
    for (int c = 0; c < 8; ++c) {
        float4 a = SG[c * 256 + tid];
        float4 b = SG[c * 256 + 128 + tid];
        acc[2*c    ] = pk2(a.x + b.x, a.y + b.y);
        acc[2*c + 1] = pk2(a.z + b.z, a.w + b.w);
    }

    // ---- acc += t @ W3 ----
#pragma unroll
    for (int k = 0; k < EMB; ++k) {
        const ull tb = pk2(t[k], t[k]);
        const ull* w2 = reinterpret_cast<const ull*>(c_W3 + k * EMB);
#pragma unroll
        for (int j2 = 0; j2 < EMB / 2; ++j2)
            acc[j2] = ffma2(tb, w2[j2], acc[j2]);
    }

    __syncthreads();   // everyone done reading gather buffer; reuse as SO

    // ---- stage silu(acc) into SO[c][edge] ----
#pragma unroll
    for (int c = 0; c < 8; ++c) {
        float a, b, cc, dd;
        upk2(acc[2*c], a, b); upk2(acc[2*c + 1], cc, dd);
        float4 v;
        v.x = silu_f(a); v.y = silu_f(b); v.z = silu_f(cc); v.w = silu_f(dd);
        SG[c * 128 + tid] = v;
    }
    __syncthreads();

    // ---- coalesced store: consecutive float4 per lane ----
    float4* out4 = reinterpret_cast<float4*>(out);
    const long long base4 = (long long)blockIdx.x * (EPB * (EMB / 4));
#pragma unroll
    for (int i = 0; i < 8; ++i) {
        int fidx = i * EPB + tid;         // 0..1023
        int el = fidx >> 3;
        int c  = fidx & 7;
        int eg = blockIdx.x * EPB + el;
        float4 v = SG[c * 128 + el];
        if (eg < E) out4[base4 + fidx] = v;
    }
}

extern "C" void kernel_launch(void* const* d_in, const int* in_sizes, int n_in,
                              void* d_out, int out_size)
{
    const float* d_dij   = (const float*)d_in[0];
    const float* d_freq  = (const float*)d_in[1];
    const float* d_emb   = (const float*)d_in[2];
    const float* d_Wrbf  = (const float*)d_in[3];
    const float* d_brbf  = (const float*)d_in[4];
    const float* d_Wd    = (const float*)d_in[5];
    const float* d_bd    = (const float*)d_in[6];
    const int*   d_Z     = (const int*)d_in[7];
    const int*   d_i     = (const int*)d_in[8];
    const int*   d_j     = (const int*)d_in[9];
    float*       out     = (float*)d_out;

    const int E = in_sizes[0];
    const int N = in_sizes[7];
    int num_z   = in_sizes[2] / EMB;
    if (num_z > MAX_Z) num_z = MAX_Z;
    if (num_z < 1)     num_z = 1;

    cudaMemcpyToSymbolAsync(c_Wr, d_Wrbf, NUM_RADIAL * EMB * sizeof(float), 0,
                            cudaMemcpyDeviceToDevice);
    cudaMemcpyToSymbolAsync(c_W3, d_Wd + (size_t)(2 * EMB) * EMB,
                            EMB * EMB * sizeof(float), 0,
                            cudaMemcpyDeviceToDevice);
    cudaMemcpyToSymbolAsync(c_br, d_brbf, EMB * sizeof(float), 0,
                            cudaMemcpyDeviceToDevice);

    precompute_emb_kernel<<<MAX_Z, EMB>>>(d_emb, d_Wd, d_bd, num_z);

    const int blocks = (E + EPB - 1) / EPB;
    dimenet_edge_kernel<<<blocks, EPB>>>(d_dij, d_freq, d_Z, d_i, d_j, out, E, N);
}

// round 7
// speedup vs baseline: 1.7415x; 1.7415x over previous
#include <cuda_runtime.h>
#include <cuda_bf16.h>

#define EMB 32
#define NUM_RADIAL 16
#define MAX_Z 128
#define EPB 128            // edges per block == threads
#define RPAD 36            // padded row stride (floats): 36 % 32 = 4 -> bank spread
#define TBL_FLOATS (2 * MAX_Z * RPAD)   // 9216 floats = 36.9 KB

typedef unsigned long long ull;

__constant__ float c_Wr[NUM_RADIAL * EMB];   // 2 KB
__constant__ float c_W3[EMB * EMB];          // 4 KB (rows 64..95 of W_dense)
__constant__ float c_br[EMB];

// Padded precomputed tables, contiguous for linear block copy:
//   g_pad[z*RPAD + j]              = emb1[z][j]  (j<32; j>=32 zero)
//   g_pad[MAX_Z*RPAD + z*RPAD + j] = emb2[z][j]
__device__ __align__(16) float g_pad[TBL_FLOATS];

__global__ void precompute_emb_kernel(const float* __restrict__ emb_table,
                                      const float* __restrict__ W_dense,
                                      const float* __restrict__ b_dense,
                                      int num_z)
{
    int z = blockIdx.x;
    int j = threadIdx.x;
    if (z >= MAX_Z || j >= EMB) return;

    float acc1 = 0.0f, acc2 = 0.0f;
    if (z < num_z) {
        acc1 = b_dense[j];
#pragma unroll
        for (int k = 0; k < EMB; ++k) {
            float e = emb_table[z * EMB + k];
            acc1 += e * W_dense[k * EMB + j];
            acc2 += e * W_dense[(EMB + k) * EMB + j];
        }
    }
    g_pad[z * RPAD + j] = acc1;
    g_pad[MAX_Z * RPAD + z * RPAD + j] = acc2;
    if (j < RPAD - EMB) {           // zero the 4 pad columns
        g_pad[z * RPAD + EMB + j] = 0.0f;
        g_pad[MAX_Z * RPAD + z * RPAD + EMB + j] = 0.0f;
    }
}

__device__ __forceinline__ ull pk2(float lo, float hi) {
    ull r; asm("mov.b64 %0, {%1, %2};" : "=l"(r) : "f"(lo), "f"(hi)); return r;
}
__device__ __forceinline__ void upk2(ull v, float& lo, float& hi) {
    asm("mov.b64 {%0, %1}, %2;" : "=f"(lo), "=f"(hi) : "l"(v));
}
__device__ __forceinline__ ull ffma2(ull a, ull b, ull c) {
    ull d; asm("fma.rn.f32x2 %0, %1, %2, %3;" : "=l"(d) : "l"(a), "l"(b), "l"(c)); return d;
}
__device__ __forceinline__ float silu_f(float s) {
    float z = __expf(-s);
    return __fdividef(s, 1.0f + z);
}

__global__ __launch_bounds__(EPB)
void dimenet_edge_kernel(const float* __restrict__ d_ij,
                         const float* __restrict__ frequencies,
                         const int*   __restrict__ Z,
                         const int*   __restrict__ idnb_i,
                         const int*   __restrict__ idnb_j,
                         float* __restrict__ out,
                         int E, int N)
{
    // Union buffer: first used as the two gather tables (2*128*36 floats),
    // later (after sync) reused as store-staging SO[e][RPAD] (128*36 floats).
    __shared__ __align__(16) float sT[TBL_FLOATS];

    const int tid = threadIdx.x;
    const int e   = blockIdx.x * EPB + tid;
    const bool valid = (e < E);
    const int es = valid ? e : (E - 1);

    // ---- scalar inputs ----
    const float d = d_ij[es];
    int ni = idnb_i[es], nj = idnb_j[es];
    ni = min(max(ni, 0), N - 1);  nj = min(max(nj, 0), N - 1);
    int zi = Z[ni], zj = Z[nj];
    zi = min(max(zi, 0), MAX_Z - 1);
    zj = min(max(zj, 0), MAX_Z - 1);
    const float f0 = frequencies[0];

    // ---- linear table copy: gmem -> smem (coalesced LDG, conflict-free STS) ----
    {
        const float4* src = reinterpret_cast<const float4*>(g_pad);
        float4* dst = reinterpret_cast<float4*>(sT);
#pragma unroll
        for (int i = 0; i < TBL_FLOATS / 4 / EPB; ++i)   // 18 iters
            dst[i * EPB + tid] = __ldg(&src[i * EPB + tid]);
    }

    // ---- rbf basis (overlaps copy latency) ----
    const float x = d * 0.2f;
    const float x2 = x * x;
    const float x4 = x2 * x2;
    const float x5 = x4 * x;
    float env = 1.0f / x + x5 * (-28.0f + x * (48.0f - 21.0f * x));
    env = (x < 1.0f) ? env : 0.0f;

    float s, c0;
    sincosf(f0 * x, &s, &c0);
    const float twoc = 2.0f * c0;

    float rbf[NUM_RADIAL];
    {
        float sm1 = 0.0f, sk = s;
#pragma unroll
        for (int k = 0; k < NUM_RADIAL; ++k) {
            rbf[k] = env * sk;
            float sp1 = twoc * sk - sm1;
            sm1 = sk; sk = sp1;
        }
    }

    // ---- t = silu(rbf @ W_rbf + b_rbf)  (constant weights, no L1) ----
    ull tp[EMB / 2];
    {
        const ull* br2 = reinterpret_cast<const ull*>(c_br);
#pragma unroll
        for (int j2 = 0; j2 < EMB / 2; ++j2) tp[j2] = br2[j2];
#pragma unroll
        for (int k = 0; k < NUM_RADIAL; ++k) {
            const ull rb = pk2(rbf[k], rbf[k]);
            const ull* w2 = reinterpret_cast<const ull*>(c_Wr + k * EMB);
#pragma unroll
            for (int j2 = 0; j2 < EMB / 2; ++j2)
                tp[j2] = ffma2(rb, w2[j2], tp[j2]);
        }
    }
    float t[EMB];
#pragma unroll
    for (int j2 = 0; j2 < EMB / 2; ++j2) {
        float a, b;
        upk2(tp[j2], a, b);
        t[2*j2] = silu_f(a); t[2*j2+1] = silu_f(b);
    }

    __syncthreads();   // tables resident

    // ---- acc = emb1[zi] + emb2[zj] from padded smem rows ----
    ull acc[EMB / 2];
    {
        const float4* r1 = reinterpret_cast<const float4*>(sT + zi * RPAD);
        const float4* r2 = reinterpret_cast<const float4*>(sT + MAX_Z * RPAD + zj * RPAD);
#pragma unroll
        for (int c = 0; c < 8; ++c) {
            float4 a = r1[c];
            float4 b = r2[c];
            acc[2*c    ] = pk2(a.x + b.x, a.y + b.y);
            acc[2*c + 1] = pk2(a.z + b.z, a.w + b.w);
        }
    }

    // ---- acc += t @ W3 ----
#pragma unroll
    for (int k = 0; k < EMB; ++k) {
        const ull tb = pk2(t[k], t[k]);
        const ull* w2 = reinterpret_cast<const ull*>(c_W3 + k * EMB);
#pragma unroll
        for (int j2 = 0; j2 < EMB / 2; ++j2)
            acc[j2] = ffma2(tb, w2[j2], acc[j2]);
    }

    __syncthreads();   // all gather reads done; reuse sT as SO staging

    // ---- stage silu(acc) at SO[tid][c], row stride RPAD floats (padded) ----
    {
        float4* so = reinterpret_cast<float4*>(sT + tid * RPAD);
#pragma unroll
        for (int c = 0; c < 8; ++c) {
            float a, b, cc, dd;
            upk2(acc[2*c], a, b); upk2(acc[2*c + 1], cc, dd);
            float4 v;
            v.x = silu_f(a); v.y = silu_f(b); v.z = silu_f(cc); v.w = silu_f(dd);
            so[c] = v;
        }
    }
    __syncthreads();

    // ---- coalesced stores: lanes write consecutive float4 ----
    float4* out4 = reinterpret_cast<float4*>(out);
    const long long base4 = (long long)blockIdx.x * (EPB * (EMB / 4));
#pragma unroll
    for (int i = 0; i < 8; ++i) {
        int fidx = i * EPB + tid;        // 0..1023 (chunk index within block)
        int el = fidx >> 3;              // local edge
        int c  = fidx & 7;               // chunk
        float4 v = *reinterpret_cast<const float4*>(sT + el * RPAD + c * 4);
        int eg = blockIdx.x * EPB + el;
        if (eg < E) out4[base4 + fidx] = v;
    }
}

extern "C" void kernel_launch(void* const* d_in, const int* in_sizes, int n_in,
                              void* d_out, int out_size)
{
    const float* d_dij   = (const float*)d_in[0];
    const float* d_freq  = (const float*)d_in[1];
    const float* d_emb   = (const float*)d_in[2];
    const float* d_Wrbf  = (const float*)d_in[3];
    const float* d_brbf  = (const float*)d_in[4];
    const float* d_Wd    = (const float*)d_in[5];
    const float* d_bd    = (const float*)d_in[6];
    const int*   d_Z     = (const int*)d_in[7];
    const int*   d_i     = (const int*)d_in[8];
    const int*   d_j     = (const int*)d_in[9];
    float*       out     = (float*)d_out;

    const int E = in_sizes[0];
    const int N = in_sizes[7];
    int num_z   = in_sizes[2] / EMB;
    if (num_z > MAX_Z) num_z = MAX_Z;
    if (num_z < 1)     num_z = 1;

    cudaMemcpyToSymbolAsync(c_Wr, d_Wrbf, NUM_RADIAL * EMB * sizeof(float), 0,
                            cudaMemcpyDeviceToDevice);
    cudaMemcpyToSymbolAsync(c_W3, d_Wd + (size_t)(2 * EMB) * EMB,
                            EMB * EMB * sizeof(float), 0,
                            cudaMemcpyDeviceToDevice);
    cudaMemcpyToSymbolAsync(c_br, d_brbf, EMB * sizeof(float), 0,
                            cudaMemcpyDeviceToDevice);

    precompute_emb_kernel<<<MAX_Z, EMB>>>(d_emb, d_Wd, d_bd, num_z);

    const int blocks = (E + EPB - 1) / EPB;
    dimenet_edge_kernel<<<blocks, EPB>>>(d_dij, d_freq, d_Z, d_i, d_j, out, E, N);
}